// round 12
// baseline (speedup 1.0000x reference)
#include <cuda_runtime.h>
#include <cuda_fp16.h>

#define KK 2
#define HH 4
#define NN 4096
#define DD 64
#define OO 64
#define NUSER 4000
#define KH (KK*HH)
#define NW (NN/32)     // 128 mask words per row
#define SPLIT 4
#define MT (NN/SPLIT)  // 1024 columns per CTA
#define NTILES (MT/64) // 16 tiles of 64 cols

// ---------------- scratch (device globals; no allocation allowed) ----------------
__device__ __align__(16) __half   g_hp[KH*NN*OO];            // h_prime fp16, 4MB
__device__ __align__(16) float    g_src[KH*NN];
__device__ __align__(16) float    g_dst[KH*NN];
__device__ __align__(16) float4   g_dpack[KH*NN];            // (d, e^d, e^{0.2d}, 0)
__device__              float     g_maxdst[KH];
__device__ __align__(16) unsigned g_mask[KK*NN*NW];          // adj bitmask, 4MB
__device__ __align__(16) float    g_num[SPLIT*KH*NN*OO];     // split partial numerators, 32MB
__device__ __align__(16) float    g_Zs[SPLIT*KH*NN];         // split partial denominators

// ---------------- small PTX helpers ----------------
__device__ __forceinline__ void cpa16(void* s, const void* g) {
    unsigned sa = (unsigned)__cvta_generic_to_shared(s);
    asm volatile("cp.async.cg.shared.global [%0], [%1], 16;" :: "r"(sa), "l"(g));
}
__device__ __forceinline__ void cpa4(void* s, const void* g) {
    unsigned sa = (unsigned)__cvta_generic_to_shared(s);
    asm volatile("cp.async.ca.shared.global [%0], [%1], 4;" :: "r"(sa), "l"(g));
}
__device__ __forceinline__ void cp_commit() { asm volatile("cp.async.commit_group;"); }

__device__ __forceinline__ void ldsm4t(unsigned& r0, unsigned& r1, unsigned& r2, unsigned& r3,
                                       unsigned saddr) {
    asm volatile("ldmatrix.sync.aligned.m8n8.x4.trans.shared.b16 {%0,%1,%2,%3}, [%4];"
                 : "=r"(r0), "=r"(r1), "=r"(r2), "=r"(r3) : "r"(saddr));
}
__device__ __forceinline__ void mma16816(float* c, unsigned a0, unsigned a1, unsigned a2,
                                         unsigned a3, unsigned b0, unsigned b1) {
    asm volatile(
        "mma.sync.aligned.m16n8k16.row.col.f32.f16.f16.f32 "
        "{%0,%1,%2,%3},{%4,%5,%6,%7},{%8,%9},{%0,%1,%2,%3};"
        : "+f"(c[0]), "+f"(c[1]), "+f"(c[2]), "+f"(c[3])
        : "r"(a0), "r"(a1), "r"(a2), "r"(a3), "r"(b0), "r"(b1));
}
__device__ __forceinline__ unsigned pack2(float a, float b) {
    __half2 h = __floats2half2_rn(a, b);
    return *reinterpret_cast<unsigned*>(&h);
}
// weight = mask ? ( (s+d>=0) ? e^{s-M} * e^d  :  e^{0.2s-M} * e^{0.2d} ) : 0
__device__ __forceinline__ float qval(float s, float ep, float en, float4 P, unsigned bit) {
    float t = s + P.x;
    float a = (t >= 0.0f) ? ep : en;
    float b = (t >= 0.0f) ? P.y : P.z;
    float q = a * b;
    return bit ? q : 0.0f;
}

// ---------------- kernel 1: pack adjacency (fp32 0/1 -> bitmask) ----------------
__global__ __launch_bounds__(256) void pack_kernel(const float* __restrict__ adj) {
    int warp = (blockIdx.x * 256 + threadIdx.x) >> 5;
    int lane = threadIdx.x & 31;
    size_t wbase = (size_t)warp * 32;
    size_t fbase = wbase * 32;
    unsigned my = 0;
    #pragma unroll
    for (int s = 0; s < 32; s++) {
        float v = adj[fbase + (size_t)s * 32 + lane];
        unsigned b = __ballot_sync(0xffffffffu, v > 0.0f);
        if (s == lane) my = b;
    }
    g_mask[wbase + lane] = my;
}

// ---------------- kernel 2: h_prime (fp16), src/dst scalars + exp precompute -----
__global__ __launch_bounds__(256) void hp_kernel(const float* __restrict__ h,
                                                 const float* __restrict__ w,
                                                 const float* __restrict__ a_src,
                                                 const float* __restrict__ a_dst) {
    const int kh = blockIdx.x >> 5;
    const int n0 = (blockIdx.x & 31) << 7;
    const int tid = threadIdx.x;
    __shared__ float ws[64 * 64];
    __shared__ float hs[128 * 65];
    __shared__ float asr[64], ads[64];

    const float4* __restrict__ wg = reinterpret_cast<const float4*>(w + (size_t)kh * DD * OO);
    float4* ws4 = reinterpret_cast<float4*>(ws);
    for (int i = tid; i < 1024; i += 256) ws4[i] = wg[i];

    const float4* __restrict__ hg = reinterpret_cast<const float4*>(h + (size_t)n0 * DD);
    for (int i = tid; i < 2048; i += 256) {
        float4 v = hg[i];
        int r = i >> 4, c = (i & 15) << 2;
        float* p = &hs[r * 65 + c];
        p[0] = v.x; p[1] = v.y; p[2] = v.z; p[3] = v.w;
    }
    if (tid < 64) { asr[tid] = a_src[kh * OO + tid]; ads[tid] = a_dst[kh * OO + tid]; }
    __syncthreads();

    const int rg = tid >> 3, cg = tid & 7;
    float acc[4][8];
    #pragma unroll
    for (int j = 0; j < 4; j++)
        #pragma unroll
        for (int c = 0; c < 8; c++) acc[j][c] = 0.0f;

    for (int d = 0; d < 64; d++) {
        float hv[4];
        #pragma unroll
        for (int j = 0; j < 4; j++) hv[j] = hs[(rg * 4 + j) * 65 + d];
        float4 wa = ws4[d * 16 + cg * 2];
        float4 wb = ws4[d * 16 + cg * 2 + 1];
        #pragma unroll
        for (int j = 0; j < 4; j++) {
            acc[j][0] += hv[j] * wa.x; acc[j][1] += hv[j] * wa.y;
            acc[j][2] += hv[j] * wa.z; acc[j][3] += hv[j] * wa.w;
            acc[j][4] += hv[j] * wb.x; acc[j][5] += hv[j] * wb.y;
            acc[j][6] += hv[j] * wb.z; acc[j][7] += hv[j] * wb.w;
        }
    }

    __half* __restrict__ hp = g_hp + (size_t)kh * NN * OO;
    float sp[4] = {0, 0, 0, 0}, dp[4] = {0, 0, 0, 0};
    #pragma unroll
    for (int j = 0; j < 4; j++) {
        int r = n0 + rg * 4 + j;
        #pragma unroll
        for (int c = 0; c < 8; c++) {
            float v = acc[j][c];
            hp[(size_t)r * OO + cg * 8 + c] = __float2half_rn(v);
            float tv = tanhf(v);
            sp[j] += tv * asr[cg * 8 + c];
            dp[j] += tv * ads[cg * 8 + c];
        }
    }
    #pragma unroll
    for (int j = 0; j < 4; j++) {
        #pragma unroll
        for (int off = 1; off < 8; off <<= 1) {
            sp[j] += __shfl_xor_sync(0xffffffffu, sp[j], off);
            dp[j] += __shfl_xor_sync(0xffffffffu, dp[j], off);
        }
    }
    if (cg == 0) {
        #pragma unroll
        for (int j = 0; j < 4; j++) {
            int r = n0 + rg * 4 + j;
            float dv = dp[j];
            g_src[kh * NN + r] = sp[j];
            g_dst[kh * NN + r] = dv;
            g_dpack[kh * NN + r] = make_float4(dv, __expf(dv), __expf(0.2f * dv), 0.0f);
        }
    }
}

// ---------------- kernel 3: max of dst per (k,h) ----------------
__global__ void maxdst_kernel() {
    __shared__ float red[256];
    int kh = blockIdx.x, tid = threadIdx.x;
    float m = -3.4e38f;
    for (int i = tid; i < NN; i += 256) m = fmaxf(m, g_dst[kh * NN + i]);
    red[tid] = m;
    __syncthreads();
    for (int s = 128; s > 0; s >>= 1) {
        if (tid < s) red[tid] = fmaxf(red[tid], red[tid + s]);
        __syncthreads();
    }
    if (tid == 0) g_maxdst[kh] = red[0];
}

// ---------------- kernel 4: fused masked-softmax attention, m-split 4-way --------
// One CTA = one (k,h) x 128-row tile x 1024-col split. 8 warps, 16 rows each.
// 3-stage ring buffer, one barrier per tile. MUFU-free weight generation.
__global__ __launch_bounds__(256, 3) void attn_kernel() {
    const int tid = threadIdx.x;
    const int sp = blockIdx.x & 3;
    const int rb = (blockIdx.x >> 2) & 31;
    const int kh = blockIdx.x >> 7;
    const int k = kh >> 2;
    const int n0 = rb << 7;
    const int mbase = sp * MT;
    const int wid = tid >> 5, lane = tid & 31;
    const int g = lane >> 2, tg = lane & 3;
    const int lr1 = (wid << 4) + g, lr2 = lr1 + 8;
    const int gr1 = n0 + lr1, gr2 = n0 + lr2;

    const float maxd = g_maxdst[kh];
    const float s1 = g_src[kh * NN + gr1];
    const float s2 = g_src[kh * NN + gr2];
    const float e1 = s1 + maxd, e2 = s2 + maxd;
    const float M1 = fmaxf(e1, 0.2f * e1);          // global row max (leaky monotone)
    const float M2 = fmaxf(e2, 0.2f * e2);
    const float EsP1 = __expf(s1 - M1),        EsN1 = __expf(0.2f * s1 - M1);
    const float EsP2 = __expf(s2 - M2),        EsN2 = __expf(0.2f * s2 - M2);

    __shared__ __align__(16) __half   hpbuf[3][64 * 72];     // 64x64 fp16, stride 72
    __shared__ __align__(16) unsigned maskbuf[3][256];       // 128 rows x 2 words
    __shared__ __align__(16) float4   dpbuf[3][64];          // (d, e^d, e^{0.2d}, _)

    const __half* __restrict__ hpg = g_hp + (size_t)kh * NN * OO;
    const unsigned* __restrict__ mg = g_mask + (size_t)k * NN * NW;
    const float4* __restrict__ dpg = g_dpack + kh * NN;

    float acc[8][4];
    #pragma unroll
    for (int i = 0; i < 8; i++)
        #pragma unroll
        for (int j = 0; j < 4; j++) acc[i][j] = 0.0f;
    float z1 = 0.0f, z2 = 0.0f;

    const int matid = lane >> 3;
    const int rowoff = ((matid & 1) << 3) + (lane & 7);
    const int colb = (matid >> 1) << 3;

    auto prefetch = [&](int it, int buf) {
        const int m0 = mbase + (it << 6);
        #pragma unroll
        for (int i = 0; i < 2; i++) {
            int c = tid + (i << 8);
            int row = c >> 3, seg = c & 7;
            cpa16(&hpbuf[buf][row * 72 + (seg << 3)],
                  hpg + (size_t)(m0 + row) * OO + (seg << 3));
        }
        {
            int row = tid >> 1, wsel = tid & 1;
            cpa4(&maskbuf[buf][tid], mg + (size_t)(n0 + row) * NW + (m0 >> 5) + wsel);
        }
        if (tid < 64) cpa16(&dpbuf[buf][tid], dpg + m0 + tid);
    };

    prefetch(0, 0);
    cp_commit();

    for (int it = 0; it < NTILES; it++) {
        const int buf = it % 3;
        if (it + 1 < NTILES) {
            prefetch(it + 1, (it + 1) % 3);
            cp_commit();
            asm volatile("cp.async.wait_group 1;");
        } else {
            asm volatile("cp.async.wait_group 0;");
        }
        __syncthreads();   // single barrier per tile; ring depth 3 makes reuse safe

        const unsigned m1a = maskbuf[buf][lr1 * 2], m1b = maskbuf[buf][lr1 * 2 + 1];
        const unsigned m2a = maskbuf[buf][lr2 * 2], m2b = maskbuf[buf][lr2 * 2 + 1];
        const unsigned hbase = (unsigned)__cvta_generic_to_shared(&hpbuf[buf][0]);

        #pragma unroll
        for (int ks = 0; ks < 4; ks++) {
            const int c0 = (ks << 4) + (tg << 1);
            float4 P0 = dpbuf[buf][c0];
            float4 P1 = dpbuf[buf][c0 + 1];
            float4 P8 = dpbuf[buf][c0 + 8];
            float4 P9 = dpbuf[buf][c0 + 9];
            const unsigned sh1 = ((ks < 2) ? m1a : m1b) >> (c0 & 31);
            const unsigned sh2 = ((ks < 2) ? m2a : m2b) >> (c0 & 31);

            float q10 = qval(s1, EsP1, EsN1, P0, sh1 & 1u);
            float q11 = qval(s1, EsP1, EsN1, P1, sh1 & 2u);
            float q18 = qval(s1, EsP1, EsN1, P8, sh1 & 256u);
            float q19 = qval(s1, EsP1, EsN1, P9, sh1 & 512u);
            float q20 = qval(s2, EsP2, EsN2, P0, sh2 & 1u);
            float q21 = qval(s2, EsP2, EsN2, P1, sh2 & 2u);
            float q28 = qval(s2, EsP2, EsN2, P8, sh2 & 256u);
            float q29 = qval(s2, EsP2, EsN2, P9, sh2 & 512u);

            z1 += (q10 + q11) + (q18 + q19);
            z2 += (q20 + q21) + (q28 + q29);

            unsigned a0 = pack2(q10, q11);
            unsigned a1 = pack2(q20, q21);
            unsigned a2 = pack2(q18, q19);
            unsigned a3 = pack2(q28, q29);

            const unsigned rbase = hbase + (unsigned)((((ks << 4) + rowoff) * 72 + colb) * 2);
            #pragma unroll
            for (int p = 0; p < 4; p++) {
                unsigned b0, b1, b2, b3;
                ldsm4t(b0, b1, b2, b3, rbase + (unsigned)(p << 5));
                mma16816(acc[2 * p],     a0, a1, a2, a3, b0, b1);
                mma16816(acc[2 * p + 1], a0, a1, a2, a3, b2, b3);
            }
        }
    }

    z1 += __shfl_xor_sync(0xffffffffu, z1, 1);
    z1 += __shfl_xor_sync(0xffffffffu, z1, 2);
    z2 += __shfl_xor_sync(0xffffffffu, z2, 1);
    z2 += __shfl_xor_sync(0xffffffffu, z2, 2);
    if (tg == 0) {
        g_Zs[(sp * KH + kh) * NN + gr1] = z1;
        g_Zs[(sp * KH + kh) * NN + gr2] = z2;
    }
    float* __restrict__ numg = g_num + ((size_t)sp * KH + kh) * NN * OO;
    #pragma unroll
    for (int ot = 0; ot < 8; ot++) {
        int cb = (ot << 3) + (tg << 1);
        numg[(size_t)gr1 * OO + cb]     = acc[ot][0];
        numg[(size_t)gr1 * OO + cb + 1] = acc[ot][1];
        numg[(size_t)gr2 * OO + cb]     = acc[ot][2];
        numg[(size_t)gr2 * OO + cb + 1] = acc[ot][3];
    }
}

// ---------------- kernel 5: split-sum, head-mean, fc, log_softmax ----------------
__global__ __launch_bounds__(256) void final_kernel(const float* __restrict__ fc_w,
                                                    const float* __restrict__ fc_b,
                                                    float* __restrict__ out) {
    int n = (blockIdx.x * 256 + threadIdx.x) >> 5;   // one warp per user node
    int lane = threadIdx.x & 31;
    if (n >= NUSER) return;
    float p0 = 0.0f, p1 = 0.0f;
    #pragma unroll
    for (int k = 0; k < KK; k++) {
        float v0 = 0.0f, v1 = 0.0f;
        #pragma unroll
        for (int h = 0; h < HH; h++) {
            int kh = k * HH + h;
            float Z = 0.0f, n0 = 0.0f, n1 = 0.0f;
            #pragma unroll
            for (int s = 0; s < SPLIT; s++) {
                Z += g_Zs[(s * KH + kh) * NN + n];
                const float* np = g_num + ((size_t)s * KH + kh) * NN * OO + (size_t)n * OO;
                n0 += np[lane];
                n1 += np[lane + 32];
            }
            float invZ = 0.25f / Z;
            v0 += n0 * invZ;
            v1 += n1 * invZ;
        }
        p0 += v0 * fc_w[k * 64 + lane]       + v1 * fc_w[k * 64 + lane + 32];
        p1 += v0 * fc_w[128 + k * 64 + lane] + v1 * fc_w[128 + k * 64 + lane + 32];
    }
    #pragma unroll
    for (int off = 16; off > 0; off >>= 1) {
        p0 += __shfl_xor_sync(0xffffffffu, p0, off);
        p1 += __shfl_xor_sync(0xffffffffu, p1, off);
    }
    if (lane == 0) {
        float l0 = p0 + fc_b[0], l1 = p1 + fc_b[1];
        float m = fmaxf(l0, l1);
        float lse = m + logf(expf(l0 - m) + expf(l1 - m));
        out[(size_t)n * 2]     = l0 - lse;
        out[(size_t)n * 2 + 1] = l1 - lse;
    }
}

// ---------------- launch ----------------
extern "C" void kernel_launch(void* const* d_in, const int* in_sizes, int n_in,
                              void* d_out, int out_size) {
    const float* h     = (const float*)d_in[0];
    const float* hadj  = (const float*)d_in[1];
    const float* w     = (const float*)d_in[2];
    const float* a_src = (const float*)d_in[3];
    const float* a_dst = (const float*)d_in[4];
    const float* fc_w  = (const float*)d_in[5];
    const float* fc_b  = (const float*)d_in[6];
    float* out = (float*)d_out;

    pack_kernel<<<4096, 256>>>(hadj);
    hp_kernel<<<KH * (NN / 128), 256>>>(h, w, a_src, a_dst);
    maxdst_kernel<<<KH, 256>>>();
    attn_kernel<<<KH * (NN / 128) * SPLIT, 256>>>();
    final_kernel<<<(NUSER * 32 + 255) / 256, 256>>>(fc_w, fc_b, out);
}

// round 16
// speedup vs baseline: 1.1993x; 1.1993x over previous
#include <cuda_runtime.h>
#include <cuda_fp16.h>

#define KK 2
#define HH 4
#define NN 4096
#define DD 64
#define OO 64
#define NUSER 4000
#define KH (KK*HH)
#define NW (NN/32)     // 128 mask words per row
#define SPLIT 4
#define MT (NN/SPLIT)  // 1024 columns per CTA
#define NTILES (MT/64) // 16 tiles of 64 cols

// ---------------- scratch (device globals; no allocation allowed) ----------------
__device__ __align__(16) __half   g_hp[KH*NN*OO];            // h_prime fp16, 4MB
__device__ __align__(16) float    g_src[KH*NN];
__device__ __align__(16) float    g_dst[KH*NN];
__device__ __align__(16) float2   g_dp2[KH*NN];              // (e^d, e^{0.2d})
__device__              float     g_maxdst[KH];
__device__ __align__(16) unsigned g_mask[KK*NN*NW];          // adj bitmask, 4MB
__device__ __align__(16) float    g_num[SPLIT*KH*NN*OO];     // split partial numerators
__device__ __align__(16) float    g_Zs[SPLIT*KH*NN];         // split partial denominators

// ---------------- small PTX helpers ----------------
__device__ __forceinline__ void cpa16(void* s, const void* g) {
    unsigned sa = (unsigned)__cvta_generic_to_shared(s);
    asm volatile("cp.async.cg.shared.global [%0], [%1], 16;" :: "r"(sa), "l"(g));
}
__device__ __forceinline__ void cpa4(void* s, const void* g) {
    unsigned sa = (unsigned)__cvta_generic_to_shared(s);
    asm volatile("cp.async.ca.shared.global [%0], [%1], 4;" :: "r"(sa), "l"(g));
}
__device__ __forceinline__ void cp_commit() { asm volatile("cp.async.commit_group;"); }

__device__ __forceinline__ void ldsm4t(unsigned& r0, unsigned& r1, unsigned& r2, unsigned& r3,
                                       unsigned saddr) {
    asm volatile("ldmatrix.sync.aligned.m8n8.x4.trans.shared.b16 {%0,%1,%2,%3}, [%4];"
                 : "=r"(r0), "=r"(r1), "=r"(r2), "=r"(r3) : "r"(saddr));
}
__device__ __forceinline__ void mma16816(float* c, unsigned a0, unsigned a1, unsigned a2,
                                         unsigned a3, unsigned b0, unsigned b1) {
    asm volatile(
        "mma.sync.aligned.m16n8k16.row.col.f32.f16.f16.f32 "
        "{%0,%1,%2,%3},{%4,%5,%6,%7},{%8,%9},{%0,%1,%2,%3};"
        : "+f"(c[0]), "+f"(c[1]), "+f"(c[2]), "+f"(c[3])
        : "r"(a0), "r"(a1), "r"(a2), "r"(a3), "r"(b0), "r"(b1));
}
__device__ __forceinline__ unsigned pack2(float a, float b) {
    __half2 h = __floats2half2_rn(a, b);
    return *reinterpret_cast<unsigned*>(&h);
}
// weight = mask ? max(e^{s-M} * e^d, e^{0.2s-M} * e^{0.2d}) : 0   (== exp(leaky(s+d)-M))
__device__ __forceinline__ float qv(float ep, float en, float2 P, unsigned bit) {
    float q = fmaxf(ep * P.x, en * P.y);
    return bit ? q : 0.0f;
}

// ---------------- kernel 1: pack adjacency (fp32 0/1 -> bitmask) ----------------
__global__ __launch_bounds__(256) void pack_kernel(const float* __restrict__ adj) {
    int warp = (blockIdx.x * 256 + threadIdx.x) >> 5;
    int lane = threadIdx.x & 31;
    size_t wbase = (size_t)warp * 32;
    size_t fbase = wbase * 32;
    unsigned my = 0;
    #pragma unroll
    for (int s = 0; s < 32; s++) {
        float v = adj[fbase + (size_t)s * 32 + lane];
        unsigned b = __ballot_sync(0xffffffffu, v > 0.0f);
        if (s == lane) my = b;
    }
    g_mask[wbase + lane] = my;
}

// ---------------- kernel 2: h_prime (fp16), src/dst scalars + exp precompute -----
__global__ __launch_bounds__(256) void hp_kernel(const float* __restrict__ h,
                                                 const float* __restrict__ w,
                                                 const float* __restrict__ a_src,
                                                 const float* __restrict__ a_dst) {
    const int kh = blockIdx.x >> 5;
    const int n0 = (blockIdx.x & 31) << 7;
    const int tid = threadIdx.x;
    __shared__ float ws[64 * 64];
    __shared__ float hs[128 * 65];
    __shared__ float asr[64], ads[64];

    const float4* __restrict__ wg = reinterpret_cast<const float4*>(w + (size_t)kh * DD * OO);
    float4* ws4 = reinterpret_cast<float4*>(ws);
    for (int i = tid; i < 1024; i += 256) ws4[i] = wg[i];

    const float4* __restrict__ hg = reinterpret_cast<const float4*>(h + (size_t)n0 * DD);
    for (int i = tid; i < 2048; i += 256) {
        float4 v = hg[i];
        int r = i >> 4, c = (i & 15) << 2;
        float* p = &hs[r * 65 + c];
        p[0] = v.x; p[1] = v.y; p[2] = v.z; p[3] = v.w;
    }
    if (tid < 64) { asr[tid] = a_src[kh * OO + tid]; ads[tid] = a_dst[kh * OO + tid]; }
    __syncthreads();

    const int rg = tid >> 3, cg = tid & 7;
    float acc[4][8];
    #pragma unroll
    for (int j = 0; j < 4; j++)
        #pragma unroll
        for (int c = 0; c < 8; c++) acc[j][c] = 0.0f;

    for (int d = 0; d < 64; d++) {
        float hv[4];
        #pragma unroll
        for (int j = 0; j < 4; j++) hv[j] = hs[(rg * 4 + j) * 65 + d];
        float4 wa = ws4[d * 16 + cg * 2];
        float4 wb = ws4[d * 16 + cg * 2 + 1];
        #pragma unroll
        for (int j = 0; j < 4; j++) {
            acc[j][0] += hv[j] * wa.x; acc[j][1] += hv[j] * wa.y;
            acc[j][2] += hv[j] * wa.z; acc[j][3] += hv[j] * wa.w;
            acc[j][4] += hv[j] * wb.x; acc[j][5] += hv[j] * wb.y;
            acc[j][6] += hv[j] * wb.z; acc[j][7] += hv[j] * wb.w;
        }
    }

    __half* __restrict__ hp = g_hp + (size_t)kh * NN * OO;
    float sp[4] = {0, 0, 0, 0}, dp[4] = {0, 0, 0, 0};
    #pragma unroll
    for (int j = 0; j < 4; j++) {
        int r = n0 + rg * 4 + j;
        #pragma unroll
        for (int c = 0; c < 8; c++) {
            float v = acc[j][c];
            hp[(size_t)r * OO + cg * 8 + c] = __float2half_rn(v);
            float tv = tanhf(v);
            sp[j] += tv * asr[cg * 8 + c];
            dp[j] += tv * ads[cg * 8 + c];
        }
    }
    #pragma unroll
    for (int j = 0; j < 4; j++) {
        #pragma unroll
        for (int off = 1; off < 8; off <<= 1) {
            sp[j] += __shfl_xor_sync(0xffffffffu, sp[j], off);
            dp[j] += __shfl_xor_sync(0xffffffffu, dp[j], off);
        }
    }
    if (cg == 0) {
        #pragma unroll
        for (int j = 0; j < 4; j++) {
            int r = n0 + rg * 4 + j;
            float dv = dp[j];
            g_src[kh * NN + r] = sp[j];
            g_dst[kh * NN + r] = dv;
            g_dp2[kh * NN + r] = make_float2(__expf(dv), __expf(0.2f * dv));
        }
    }
}

// ---------------- kernel 3: max of dst per (k,h) ----------------
__global__ void maxdst_kernel() {
    __shared__ float red[256];
    int kh = blockIdx.x, tid = threadIdx.x;
    float m = -3.4e38f;
    for (int i = tid; i < NN; i += 256) m = fmaxf(m, g_dst[kh * NN + i]);
    red[tid] = m;
    __syncthreads();
    for (int s = 128; s > 0; s >>= 1) {
        if (tid < s) red[tid] = fmaxf(red[tid], red[tid + s]);
        __syncthreads();
    }
    if (tid == 0) g_maxdst[kh] = red[0];
}

// ---------------- kernel 4: fused masked-softmax attention -----------------------
// One CTA = (k,h) x 128-row tile x 1024-col split. 4 warps x 32 rows (2 MMA row
// tiles per warp) -> each B-fragment ldmatrix feeds 2 row tiles (halved L1).
// Max-form fp32 weight gen (no FADD/FSEL chain); Z via ones-column MMA.
__global__ __launch_bounds__(128, 4) void attn_kernel() {
    const int tid = threadIdx.x;
    const int sp = blockIdx.x & 3;
    const int rb = (blockIdx.x >> 2) & 31;
    const int kh = blockIdx.x >> 7;
    const int k = kh >> 2;
    const int n0 = rb << 7;
    const int mbase = sp * MT;
    const int wid = tid >> 5, lane = tid & 31;
    const int g = lane >> 2, tg = lane & 3;
    const int r1a = (wid << 5) + g;         // local rows: warp owns [wid*32, wid*32+32)
    const int r2a = r1a + 8;
    const int r1b = r1a + 16;
    const int r2b = r1a + 24;
    const int gr1a = n0 + r1a, gr2a = n0 + r2a, gr1b = n0 + r1b, gr2b = n0 + r2b;

    const float maxd = g_maxdst[kh];
    const float s1a = g_src[kh * NN + gr1a];
    const float s2a = g_src[kh * NN + gr2a];
    const float s1b = g_src[kh * NN + gr1b];
    const float s2b = g_src[kh * NN + gr2b];
    // global row max: M = leaky(s + maxd)  (leaky monotone)
    const float M1a = fmaxf(s1a + maxd, 0.2f * (s1a + maxd));
    const float M2a = fmaxf(s2a + maxd, 0.2f * (s2a + maxd));
    const float M1b = fmaxf(s1b + maxd, 0.2f * (s1b + maxd));
    const float M2b = fmaxf(s2b + maxd, 0.2f * (s2b + maxd));
    const float EP1a = __expf(s1a - M1a), EN1a = __expf(0.2f * s1a - M1a);
    const float EP2a = __expf(s2a - M2a), EN2a = __expf(0.2f * s2a - M2a);
    const float EP1b = __expf(s1b - M1b), EN1b = __expf(0.2f * s1b - M1b);
    const float EP2b = __expf(s2b - M2b), EN2b = __expf(0.2f * s2b - M2b);

    __shared__ __align__(16) __half   hpbuf[3][64 * 72];     // 64x64 fp16, stride 72
    __shared__ __align__(16) unsigned maskbuf[3][256];       // 128 rows x 2 words
    __shared__ __align__(16) float2   dp2buf[3][64];         // (e^d, e^{0.2d})

    const __half* __restrict__ hpg = g_hp + (size_t)kh * NN * OO;
    const unsigned* __restrict__ mg = g_mask + (size_t)k * NN * NW;
    const float2* __restrict__ dpg = g_dp2 + kh * NN;

    float accA[8][4], accB[8][4], za[4], zb[4];
    #pragma unroll
    for (int i = 0; i < 8; i++)
        #pragma unroll
        for (int j = 0; j < 4; j++) { accA[i][j] = 0.0f; accB[i][j] = 0.0f; }
    #pragma unroll
    for (int j = 0; j < 4; j++) { za[j] = 0.0f; zb[j] = 0.0f; }

    const int matid = lane >> 3;
    const int rowoff = ((matid & 1) << 3) + (lane & 7);
    const int colb = (matid >> 1) << 3;
    const unsigned ONE2 = 0x3C003C00u;       // half2(1.0, 1.0)

    auto prefetch = [&](int it, int buf) {
        const int m0 = mbase + (it << 6);
        #pragma unroll
        for (int i = 0; i < 4; i++) {
            int c = tid + (i << 7);
            int row = c >> 3, seg = c & 7;
            cpa16(&hpbuf[buf][row * 72 + (seg << 3)],
                  hpg + (size_t)(m0 + row) * OO + (seg << 3));
        }
        #pragma unroll
        for (int i = 0; i < 2; i++) {
            int c = tid + (i << 7);
            int row = c >> 1, wsel = c & 1;
            cpa4(&maskbuf[buf][c], mg + (size_t)(n0 + row) * NW + (m0 >> 5) + wsel);
        }
        if (tid < 32) cpa16(&dp2buf[buf][tid * 2], dpg + m0 + tid * 2);
    };

    prefetch(0, 0);
    cp_commit();

    for (int it = 0; it < NTILES; it++) {
        const int buf = it % 3;
        if (it + 1 < NTILES) {
            prefetch(it + 1, (it + 1) % 3);
            cp_commit();
            asm volatile("cp.async.wait_group 1;");
        } else {
            asm volatile("cp.async.wait_group 0;");
        }
        __syncthreads();   // single barrier per tile; ring depth 3 makes reuse safe

        const unsigned w1a0 = maskbuf[buf][r1a * 2], w1a1 = maskbuf[buf][r1a * 2 + 1];
        const unsigned w2a0 = maskbuf[buf][r2a * 2], w2a1 = maskbuf[buf][r2a * 2 + 1];
        const unsigned w1b0 = maskbuf[buf][r1b * 2], w1b1 = maskbuf[buf][r1b * 2 + 1];
        const unsigned w2b0 = maskbuf[buf][r2b * 2], w2b1 = maskbuf[buf][r2b * 2 + 1];
        const unsigned hbase = (unsigned)__cvta_generic_to_shared(&hpbuf[buf][0]);

        #pragma unroll
        for (int ks = 0; ks < 4; ks++) {
            const int c0 = (ks << 4) + (tg << 1);
            float2 P0 = dp2buf[buf][c0];
            float2 P1 = dp2buf[buf][c0 + 1];
            float2 P8 = dp2buf[buf][c0 + 8];
            float2 P9 = dp2buf[buf][c0 + 9];
            const int sh = c0 & 31;
            const unsigned x1a = ((ks < 2) ? w1a0 : w1a1) >> sh;
            const unsigned x2a = ((ks < 2) ? w2a0 : w2a1) >> sh;
            const unsigned x1b = ((ks < 2) ? w1b0 : w1b1) >> sh;
            const unsigned x2b = ((ks < 2) ? w2b0 : w2b1) >> sh;

            // A-fragments (m16n8k16): a0/a2 row g (k-lo/k-hi), a1/a3 row g+8
            unsigned a0 = pack2(qv(EP1a, EN1a, P0, x1a & 1u),   qv(EP1a, EN1a, P1, x1a & 2u));
            unsigned a1 = pack2(qv(EP2a, EN2a, P0, x2a & 1u),   qv(EP2a, EN2a, P1, x2a & 2u));
            unsigned a2 = pack2(qv(EP1a, EN1a, P8, x1a & 256u), qv(EP1a, EN1a, P9, x1a & 512u));
            unsigned a3 = pack2(qv(EP2a, EN2a, P8, x2a & 256u), qv(EP2a, EN2a, P9, x2a & 512u));
            unsigned c0r = pack2(qv(EP1b, EN1b, P0, x1b & 1u),   qv(EP1b, EN1b, P1, x1b & 2u));
            unsigned c1r = pack2(qv(EP2b, EN2b, P0, x2b & 1u),   qv(EP2b, EN2b, P1, x2b & 2u));
            unsigned c2r = pack2(qv(EP1b, EN1b, P8, x1b & 256u), qv(EP1b, EN1b, P9, x1b & 512u));
            unsigned c3r = pack2(qv(EP2b, EN2b, P8, x2b & 256u), qv(EP2b, EN2b, P9, x2b & 512u));

            // Z = row sums of the same half weights (exact, consistent with numerator)
            mma16816(za, a0, a1, a2, a3, ONE2, ONE2);
            mma16816(zb, c0r, c1r, c2r, c3r, ONE2, ONE2);

            const unsigned rbase = hbase + (unsigned)((((ks << 4) + rowoff) * 72 + colb) * 2);
            #pragma unroll
            for (int p = 0; p < 4; p++) {
                unsigned b0, b1, b2, b3;
                ldsm4t(b0, b1, b2, b3, rbase + (unsigned)(p << 5));
                mma16816(accA[2 * p],     a0, a1, a2, a3, b0, b1);
                mma16816(accA[2 * p + 1], a0, a1, a2, a3, b2, b3);
                mma16816(accB[2 * p],     c0r, c1r, c2r, c3r, b0, b1);
                mma16816(accB[2 * p + 1], c0r, c1r, c2r, c3r, b2, b3);
            }
        }
    }

    // Z: every lane of a row group holds the same value in za/zb (ones-B)
    if (tg == 0) {
        float* zp = g_Zs + (sp * KH + kh) * NN;
        zp[gr1a] = za[0];
        zp[gr2a] = za[2];
        zp[gr1b] = zb[0];
        zp[gr2b] = zb[2];
    }
    float* __restrict__ numg = g_num + ((size_t)sp * KH + kh) * NN * OO;
    #pragma unroll
    for (int ot = 0; ot < 8; ot++) {
        int cb = (ot << 3) + (tg << 1);
        numg[(size_t)gr1a * OO + cb]     = accA[ot][0];
        numg[(size_t)gr1a * OO + cb + 1] = accA[ot][1];
        numg[(size_t)gr2a * OO + cb]     = accA[ot][2];
        numg[(size_t)gr2a * OO + cb + 1] = accA[ot][3];
        numg[(size_t)gr1b * OO + cb]     = accB[ot][0];
        numg[(size_t)gr1b * OO + cb + 1] = accB[ot][1];
        numg[(size_t)gr2b * OO + cb]     = accB[ot][2];
        numg[(size_t)gr2b * OO + cb + 1] = accB[ot][3];
    }
}

// ---------------- kernel 5: split-sum, head-mean, fc, log_softmax ----------------
__global__ __launch_bounds__(256) void final_kernel(const float* __restrict__ fc_w,
                                                    const float* __restrict__ fc_b,
                                                    float* __restrict__ out) {
    int n = (blockIdx.x * 256 + threadIdx.x) >> 5;   // one warp per user node
    int lane = threadIdx.x & 31;
    if (n >= NUSER) return;
    float p0 = 0.0f, p1 = 0.0f;
    #pragma unroll
    for (int k = 0; k < KK; k++) {
        float v0 = 0.0f, v1 = 0.0f;
        #pragma unroll
        for (int h = 0; h < HH; h++) {
            int kh = k * HH + h;
            float Z = 0.0f, n0 = 0.0f, n1 = 0.0f;
            #pragma unroll
            for (int s = 0; s < SPLIT; s++) {
                Z += g_Zs[(s * KH + kh) * NN + n];
                const float* np = g_num + ((size_t)s * KH + kh) * NN * OO + (size_t)n * OO;
                n0 += np[lane];
                n1 += np[lane + 32];
            }
            float invZ = 0.25f / Z;
            v0 += n0 * invZ;
            v1 += n1 * invZ;
        }
        p0 += v0 * fc_w[k * 64 + lane]       + v1 * fc_w[k * 64 + lane + 32];
        p1 += v0 * fc_w[128 + k * 64 + lane] + v1 * fc_w[128 + k * 64 + lane + 32];
    }
    #pragma unroll
    for (int off = 16; off > 0; off >>= 1) {
        p0 += __shfl_xor_sync(0xffffffffu, p0, off);
        p1 += __shfl_xor_sync(0xffffffffu, p1, off);
    }
    if (lane == 0) {
        float l0 = p0 + fc_b[0], l1 = p1 + fc_b[1];
        float m = fmaxf(l0, l1);
        float lse = m + logf(expf(l0 - m) + expf(l1 - m));
        out[(size_t)n * 2]     = l0 - lse;
        out[(size_t)n * 2 + 1] = l1 - lse;
    }
}

// ---------------- launch ----------------
extern "C" void kernel_launch(void* const* d_in, const int* in_sizes, int n_in,
                              void* d_out, int out_size) {
    const float* h     = (const float*)d_in[0];
    const float* hadj  = (const float*)d_in[1];
    const float* w     = (const float*)d_in[2];
    const float* a_src = (const float*)d_in[3];
    const float* a_dst = (const float*)d_in[4];
    const float* fc_w  = (const float*)d_in[5];
    const float* fc_b  = (const float*)d_in[6];
    float* out = (float*)d_out;

    pack_kernel<<<4096, 256>>>(hadj);
    hp_kernel<<<KH * (NN / 128), 256>>>(h, w, a_src, a_dst);
    maxdst_kernel<<<KH, 256>>>();
    attn_kernel<<<KH * (NN / 128) * SPLIT, 128>>>();
    final_kernel<<<(NUSER * 32 + 255) / 256, 256>>>(fc_w, fc_b, out);
}